// round 13
// baseline (speedup 1.0000x reference)
#include <cuda_runtime.h>
#include <cstdint>
#include <cstddef>

// ---------------------------------------------------------------------------
// Model_80985903333896: MoNet-style graph CNN.  B=8, M=4096, W=128, C=32.
// THREE launches:
//   K1 mega   : P1 ygemm0+attn | P2 gather0+BN0 | P3 ygemm1 | P4 gather1+BN1
//               (persistent, software grid barriers — exact R6 configuration)
//   K2 fc1    : BN1+relu fused, 2048 blocks (32out x 512k), .cg weight stream
//   K3 fc2    : -> out (8,53)
// Split gives per-phase ncu visibility (mega aggregate hid fc1 for 6 rounds).
// ---------------------------------------------------------------------------

#define EPSBN 1e-5f
typedef unsigned long long ull;

// ------------------------- scratch (__device__ globals) --------------------
__device__ float g_w0e[65536];
__device__ float g_w1e[65536];
__device__ int   g_nbr[65536];
__device__ float g_y1[1048576];   // (B*M, 32)
__device__ float g_y2[1048576];
__device__ float g_h1[1048576];
__device__ float g_h2[1048576];
__device__ float g_sum0[32], g_sq0[32], g_sum1[32], g_sq1[32];
__device__ float g_fc1acc[2048];  // (8, 256)
__device__ unsigned g_bar_count = 0;
__device__ unsigned g_bar_gen   = 0;

// ------------------------- packed f32x2 FMA helpers ------------------------
__device__ __forceinline__ ull pk2(float x, float y) {
    ull r; asm("mov.b64 %0, {%1, %2};" : "=l"(r) : "f"(x), "f"(y)); return r;
}
__device__ __forceinline__ void ffma2(ull& d, ull a, ull b) {
    asm("fma.rn.f32x2 %0, %1, %2, %0;" : "+l"(d) : "l"(a), "l"(b));
}
__device__ __forceinline__ float2 unpk(ull v) {
    float2 r; asm("mov.b64 {%0, %1}, %2;" : "=f"(r.x), "=f"(r.y) : "l"(v)); return r;
}
// L1-bypass vector load (stream-once data; keeps L1 for LDS/acts)
__device__ __forceinline__ float4 ldcg4(const float* p) {
    float4 v;
    asm("ld.global.cg.v4.f32 {%0,%1,%2,%3}, [%4];"
        : "=f"(v.x), "=f"(v.y), "=f"(v.z), "=f"(v.w) : "l"(p));
    return v;
}

// ------------------------- software grid barrier ---------------------------
__device__ __forceinline__ void grid_barrier() {
    __syncthreads();
    if (threadIdx.x == 0) {
        __threadfence();
        unsigned gen = *((volatile unsigned*)&g_bar_gen);
        if (atomicAdd(&g_bar_count, 1u) == gridDim.x - 1u) {
            *((volatile unsigned*)&g_bar_count) = 0u;
            __threadfence();
            atomicExch(&g_bar_gen, gen + 1u);
        } else {
            while (*((volatile unsigned*)&g_bar_gen) == gen) __nanosleep(64);
            __threadfence();
        }
    }
    __syncthreads();
}

// ===========================================================================
// attn unit (256 edges): gaussian mixture -> 16-lane softmax -> dedup.
// Unit 0 also zero-inits the global accumulators (consumed after barrier 1).
// ===========================================================================
__device__ __forceinline__ void attn_unit(int bx,
    const float* __restrict__ pseudo, const int* __restrict__ L_idx,
    const float* __restrict__ edge_w, const float* __restrict__ edge_b,
    const float* __restrict__ mu0, const float* __restrict__ sg0,
    const float* __restrict__ mu1, const float* __restrict__ sg1)
{
    int tid = threadIdx.x;
    if (bx == 0) {
        if (tid < 32) {
            g_sum0[tid] = 0.f; g_sq0[tid] = 0.f;
            g_sum1[tid] = 0.f; g_sq1[tid] = 0.f;
        }
        for (int i = tid; i < 2048; i += 256) g_fc1acc[i] = 0.f;
    }
    int e = bx * 256 + tid;
    int i = e & 15;

    float p0 = pseudo[2 * e], p1 = pseudo[2 * e + 1];
    float emb[5];
#pragma unroll
    for (int d = 0; d < 5; d++)
        emb[d] = edge_w[2 * d] * p0 + edge_w[2 * d + 1] * p1 + edge_b[d];

    float w0 = 0.f, w1 = 0.f;
#pragma unroll
    for (int j = 0; j < 4; j++) {
        float q0 = 0.f, q1 = 0.f;
#pragma unroll
        for (int d = 0; d < 5; d++) {
            float u0 = emb[d] - mu0[j * 5 + d]; q0 += u0 * u0 * sg0[j * 5 + d];
            float u1 = emb[d] - mu1[j * 5 + d]; q1 += u1 * u1 * sg1[j * 5 + d];
        }
        w0 += expf(-0.5f * q0);
        w1 += expf(-0.5f * q1);
    }

    float m0 = w0, m1 = w1;
#pragma unroll
    for (int s = 8; s; s >>= 1) {
        m0 = fmaxf(m0, __shfl_xor_sync(0xffffffffu, m0, s, 16));
        m1 = fmaxf(m1, __shfl_xor_sync(0xffffffffu, m1, s, 16));
    }
    float e0 = expf(w0 - m0), e1 = expf(w1 - m1);
    float s0 = e0, s1 = e1;
#pragma unroll
    for (int s = 8; s; s >>= 1) {
        s0 += __shfl_xor_sync(0xffffffffu, s0, s, 16);
        s1 += __shfl_xor_sync(0xffffffffu, s1, s, 16);
    }
    float a0 = e0 / s0, a1 = e1 / s1;

    int nb = L_idx[e] & 4095;
    bool dup = false;
#pragma unroll
    for (int j = 0; j < 16; j++) {
        int nj = __shfl_sync(0xffffffffu, nb, j, 16);
        dup |= (j > i) && (nj == nb);
    }
    g_w0e[e] = dup ? 0.f : a0;
    g_w1e[e] = dup ? 0.f : a1;
    g_nbr[e] = nb;
}

// ===========================================================================
// ygemm unit: 32 rows x 64 outs, K chunked by 32 through smem.
// Thread tile 1 row x 8 outs (acc 8 f32x2). Epilogue staged for coalesced
// stores. aux[0..31]=BN scale, aux[32..63]=BN shift (precomputed per phase).
// ===========================================================================
template<int KDIM, bool DO_BN>
__device__ __forceinline__ void ygemm_unit(int u,
    const float* __restrict__ src,
    const float* __restrict__ w1, const float* __restrict__ w2,
    const float* __restrict__ b1, const float* __restrict__ b2,
    float* s, const float* aux)
{
    constexpr int PADC = 36;
    float* sx = s;                 // 32*36
    float* sw = s + 32 * PADC;     // 64*36
    int tid = threadIdx.x;
    int warp = tid >> 5, lane = tid & 31;
    int r2 = lane >> 3, o = lane & 7;
    int rowbase = u * 32;
    int row = warp * 4 + r2;

    ull acc[8];
#pragma unroll
    for (int j = 0; j < 8; j++) acc[j] = 0ull;

#pragma unroll
    for (int c = 0; c < KDIM / 32; c++) {
        __syncthreads();   // also protects prev unit's epilogue reads
        {
            int r = tid >> 3, kq = tid & 7;
            float4 v = *(const float4*)(src + (size_t)(rowbase + r) * KDIM + c * 32 + kq * 4);
            if (DO_BN) {
                int k0 = kq * 4;   // KDIM==32 here
                v.x = fmaxf(0.f, fmaf(v.x, aux[k0],     aux[32 + k0]));
                v.y = fmaxf(0.f, fmaf(v.y, aux[k0 + 1], aux[32 + k0 + 1]));
                v.z = fmaxf(0.f, fmaf(v.z, aux[k0 + 2], aux[32 + k0 + 2]));
                v.w = fmaxf(0.f, fmaf(v.w, aux[k0 + 3], aux[32 + k0 + 3]));
            }
            *(float4*)&sx[r * PADC + kq * 4] = v;
        }
#pragma unroll
        for (int i = 0; i < 2; i++) {
            int idx = tid + i * 256;
            int oo = idx >> 3, kq = idx & 7;
            const float* wsrc = (oo < 32) ? (w1 + oo * KDIM) : (w2 + (oo - 32) * KDIM);
            *(float4*)&sw[oo * PADC + kq * 4] = *(const float4*)(wsrc + c * 32 + kq * 4);
        }
        __syncthreads();

#pragma unroll
        for (int kk = 0; kk < 8; kk++) {
            float4 xv = *(const float4*)&sx[row * PADC + kk * 4];
            ull x01 = pk2(xv.x, xv.y), x23 = pk2(xv.z, xv.w);
#pragma unroll
            for (int jj = 0; jj < 8; jj++) {
                float4 wv = *(const float4*)&sw[(o + 8 * jj) * PADC + kk * 4];
                ffma2(acc[jj], x01, pk2(wv.x, wv.y));
                ffma2(acc[jj], x23, pk2(wv.z, wv.w));
            }
        }
    }
    __syncthreads();
#pragma unroll
    for (int jj = 0; jj < 8; jj++) {
        float2 v = unpk(acc[jj]);
        s[row * 65 + o + 8 * jj] = v.x + v.y;
    }
    __syncthreads();
#pragma unroll
    for (int i = 0; i < 2; i++) {
        int idx = tid + i * 256;     // 512 float4 = 32 rows x 16
        int r = idx >> 4, q = idx & 15;
        int c0 = q * 4;
        float4 v;
        v.x = s[r * 65 + c0];
        v.y = s[r * 65 + c0 + 1];
        v.z = s[r * 65 + c0 + 2];
        v.w = s[r * 65 + c0 + 3];
        int grow = rowbase + r;
        if (c0 < 32) {
            *(float4*)&g_y1[grow * 32 + c0] = v;
        } else {
            int oc = c0 - 32;
            v.x += b1[oc]     + b2[oc];
            v.y += b1[oc + 1] + b2[oc + 1];
            v.z += b1[oc + 2] + b2[oc + 2];
            v.w += b1[oc + 3] + b2[oc + 3];
            *(float4*)&g_y2[grow * 32 + oc] = v;
        }
    }
}

// ===========================================================================
// gather phase: warp-unit = (node m, batch pair). 16384 units grid-strided
// over all warps. lane = channel. + BN stats (block-reduced, 1 atomic set).
// ===========================================================================
template<int LAYER>
__device__ __forceinline__ void gather_phase(float* red)
{
    const float* __restrict__ weff = (LAYER == 0) ? g_w0e : g_w1e;
    float* __restrict__ h   = (LAYER == 0) ? g_h1 : g_h2;
    float* gsum = (LAYER == 0) ? g_sum0 : g_sum1;
    float* gsq  = (LAYER == 0) ? g_sq0  : g_sq1;

    int tid = threadIdx.x, lane = tid & 31, warp = tid >> 5;
    if (tid < 64) red[tid] = 0.f;
    __syncthreads();

    int nw = gridDim.x * 8;
    float lsum = 0.f, lsq = 0.f;
    for (int u = blockIdx.x * 8 + warp; u < 16384; u += nw) {
        int m = u >> 2;
        int b0 = (u & 3) << 1;
        float wv = 0.f; int nv = 0;
        if (lane < 16) {
            wv = weff[m * 16 + lane];
            nv = g_nbr[m * 16 + lane];
        }
        int row0 = (b0 << 12) + m;
        float a0 = g_y2[(size_t)row0 * 32 + lane];
        float a1 = g_y2[(size_t)(row0 + 4096) * 32 + lane];
#pragma unroll
        for (int i = 0; i < 16; i++) {
            float wi = __shfl_sync(0xffffffffu, wv, i);
            int   ni = __shfl_sync(0xffffffffu, nv, i);
            int rn = (b0 << 12) + ni;
            a0 = fmaf(wi, g_y1[(size_t)rn * 32 + lane], a0);
            a1 = fmaf(wi, g_y1[(size_t)(rn + 4096) * 32 + lane], a1);
        }
        h[(size_t)row0 * 32 + lane] = a0;
        h[(size_t)(row0 + 4096) * 32 + lane] = a1;
        lsum += a0 + a1;
        lsq  += a0 * a0 + a1 * a1;
    }
    atomicAdd(&red[lane], lsum);
    atomicAdd(&red[32 + lane], lsq);
    __syncthreads();
    if (tid < 32) {
        atomicAdd(&gsum[tid], red[tid]);
        atomicAdd(&gsq[tid],  red[32 + tid]);
    }
}

// ===========================================================================
// K1: mega-kernel = P1..P4 only (exact R6 configuration)
// ===========================================================================
__global__ void __launch_bounds__(256, 3) mega_kernel(
    const float* __restrict__ x,
    const float* __restrict__ pseudo, const int* __restrict__ L_idx,
    const float* __restrict__ edge_w, const float* __restrict__ edge_b,
    const float* __restrict__ mu0, const float* __restrict__ sg0,
    const float* __restrict__ mu1, const float* __restrict__ sg1,
    const float* __restrict__ l1w0, const float* __restrict__ l1b0,
    const float* __restrict__ l2w0, const float* __restrict__ l2b0,
    const float* __restrict__ l1w1, const float* __restrict__ l1b1,
    const float* __restrict__ l2w1, const float* __restrict__ l2b1,
    const float* __restrict__ bn_g0, const float* __restrict__ bn_b0)
{
    __shared__ __align__(16) float s[4608];
    __shared__ float aux[64];
    __shared__ float red[64];
    int tid = threadIdx.x;

    // ---- P1: ygemm0 (units 0..1023) + attn (1024..1279) ----
    for (int u = blockIdx.x; u < 1280; u += gridDim.x) {
        if (u < 1024)
            ygemm_unit<128, false>(u, x, l1w0, l2w0, l1b0, l2b0, s, aux);
        else
            attn_unit(u - 1024, pseudo, L_idx, edge_w, edge_b, mu0, sg0, mu1, sg1);
    }
    grid_barrier();

    // ---- P2: gather0 + BN0 stats ----
    gather_phase<0>(red);
    grid_barrier();

    // ---- P3: ygemm1 (BN0 applied on load) ----
    if (tid < 32) {
        const float inv_n = 1.0f / 32768.0f;
        float mean = g_sum0[tid] * inv_n;
        float var  = g_sq0[tid] * inv_n - mean * mean;
        float sc   = bn_g0[tid] * rsqrtf(var + EPSBN);
        aux[tid] = sc;
        aux[32 + tid] = bn_b0[tid] - mean * sc;
    }
    __syncthreads();
    for (int u = blockIdx.x; u < 1024; u += gridDim.x)
        ygemm_unit<32, true>(u, g_h1, l1w1, l2w1, l1b1, l2b1, s, aux);
    grid_barrier();

    // ---- P4: gather1 + BN1 stats ----
    gather_phase<1>(red);
}

// ===========================================================================
// K2: fc1, BN1+relu fused.  2048 blocks (og 0..7 x kc 0..255), 256 threads.
// Acts staged once/block (8 b x 512 k, stride 520); weights streamed .cg
// (L1 bypass — stream-once).  Warp = 4 outs; lane-halves split batches;
// acc 4 outs x 4 b f32x2. Butterfly distribute-reduce; 32 atomics/warp.
// ===========================================================================
__global__ void __launch_bounds__(256) fc1_kernel(
    const float* __restrict__ fc1w,
    const float* __restrict__ bng, const float* __restrict__ bnb)
{
    __shared__ __align__(16) float s[4160];   // 8 x 520
    __shared__ float aux[64];

    int tid = threadIdx.x, lane = tid & 31, warp = tid >> 5;
    int l16 = lane & 15;
    int bbase = (lane >> 4) * 4;
    int og = blockIdx.x >> 8;        // 0..7
    int kc = blockIdx.x & 255;       // 0..255
    int kbase = kc * 512;

    if (tid < 32) {
        const float inv_n = 1.0f / 32768.0f;
        float mean = g_sum1[tid] * inv_n;
        float var  = g_sq1[tid] * inv_n - mean * mean;
        float sc   = bng[tid] * rsqrtf(var + EPSBN);
        aux[tid] = sc;
        aux[32 + tid] = bnb[tid] - mean * sc;
    }
    __syncthreads();

    // stage acts: 8 batches x 512 k, BN+relu (acts read .cg — L2 reuse only)
#pragma unroll
    for (int i = 0; i < 4; i++) {
        int idx = tid + i * 256;
        int b = idx >> 7, kq = idx & 127;
        float4 v = ldcg4(&g_h2[(size_t)b * 131072 + kbase + kq * 4]);
        int c0 = (kq * 4) & 31;
        v.x = fmaxf(0.f, fmaf(v.x, aux[c0],     aux[32 + c0]));
        v.y = fmaxf(0.f, fmaf(v.y, aux[c0 + 1], aux[32 + c0 + 1]));
        v.z = fmaxf(0.f, fmaf(v.z, aux[c0 + 2], aux[32 + c0 + 2]));
        v.w = fmaxf(0.f, fmaf(v.w, aux[c0 + 3], aux[32 + c0 + 3]));
        *(float4*)&s[b * 520 + kq * 4] = v;
    }
    __syncthreads();

    const float* wp = fc1w + (size_t)(og * 32 + warp * 4) * 131072 + kbase;
    ull acc[4][4];
#pragma unroll
    for (int o4 = 0; o4 < 4; o4++)
#pragma unroll
        for (int bb = 0; bb < 4; bb++) acc[o4][bb] = 0ull;

#pragma unroll
    for (int t = 0; t < 8; t++) {
        int k0 = t * 64 + l16 * 4;
        float4 w[4], a[4];
#pragma unroll
        for (int o4 = 0; o4 < 4; o4++)
            w[o4] = ldcg4(wp + (size_t)o4 * 131072 + k0);
#pragma unroll
        for (int bb = 0; bb < 4; bb++)
            a[bb] = *(const float4*)&s[(bbase + bb) * 520 + k0];
#pragma unroll
        for (int o4 = 0; o4 < 4; o4++) {
            ull w01 = pk2(w[o4].x, w[o4].y), w23 = pk2(w[o4].z, w[o4].w);
#pragma unroll
            for (int bb = 0; bb < 4; bb++) {
                ffma2(acc[o4][bb], w01, pk2(a[bb].x, a[bb].y));
                ffma2(acc[o4][bb], w23, pk2(a[bb].z, a[bb].w));
            }
        }
    }

    // butterfly distribute-reduce within each 16-lane half
    float v[16];
#pragma unroll
    for (int o4 = 0; o4 < 4; o4++)
#pragma unroll
        for (int bb = 0; bb < 4; bb++) {
            float2 t2 = unpk(acc[o4][bb]);
            v[o4 * 4 + bb] = t2.x + t2.y;
        }
#pragma unroll
    for (int sr = 8; sr >= 1; sr >>= 1) {
        bool up = (l16 & sr) != 0;
#pragma unroll
        for (int i = 0; i < sr; i++) {
            float send = up ? v[i] : v[i + sr];
            float got  = __shfl_xor_sync(0xffffffffu, send, sr);
            v[i] = (up ? v[i + sr] : v[i]) + got;
        }
    }
    int o4 = l16 >> 2, bb = l16 & 3;
    atomicAdd(&g_fc1acc[(bbase + bb) * 256 + og * 32 + warp * 4 + o4], v[0]);
}

// ===========================================================================
// K3: relu(fc1acc + fc1b) @ fc2w^T + fc2b -> out (8,53). Single block.
// ===========================================================================
__global__ void __launch_bounds__(448) fc2_kernel(
    const float* __restrict__ fc1b,
    const float* __restrict__ fc2w, const float* __restrict__ fc2b,
    float* __restrict__ out)
{
    __shared__ float sf[2048];
    int tid = threadIdx.x;
    for (int i = tid; i < 2048; i += 448)
        sf[i] = fmaxf(0.f, g_fc1acc[i] + fc1b[i & 255]);
    __syncthreads();
    if (tid < 424) {
        int b = tid / 53, o = tid - b * 53;
        float acc = fc2b[o];
        const float* w = fc2w + o * 256;
        const float* f = sf + b * 256;
#pragma unroll 8
        for (int k = 0; k < 256; k++) acc += w[k] * f[k];
        out[tid] = acc;
    }
}

// ===========================================================================
extern "C" void kernel_launch(void* const* d_in, const int* in_sizes, int n_in,
                              void* d_out, int out_size)
{
    const float* x      = (const float*)d_in[0];
    const float* pseudo = (const float*)d_in[1];
    const int*   L_idx  = (const int*)  d_in[2];
    const float* edge_w = (const float*)d_in[3];
    const float* edge_b = (const float*)d_in[4];
    const float* mu0    = (const float*)d_in[5];
    const float* sg0    = (const float*)d_in[6];
    const float* mu1    = (const float*)d_in[7];
    const float* sg1    = (const float*)d_in[8];
    const float* l1w0   = (const float*)d_in[9];
    const float* l1b0   = (const float*)d_in[10];
    const float* l2w0   = (const float*)d_in[11];
    const float* l2b0   = (const float*)d_in[12];
    const float* l1w1   = (const float*)d_in[13];
    const float* l1b1   = (const float*)d_in[14];
    const float* l2w1   = (const float*)d_in[15];
    const float* l2b1   = (const float*)d_in[16];
    const float* bn_g0  = (const float*)d_in[17];
    const float* bn_b0  = (const float*)d_in[18];
    const float* bn_g1  = (const float*)d_in[19];
    const float* bn_b1  = (const float*)d_in[20];
    const float* fc1w   = (const float*)d_in[21];
    const float* fc1b   = (const float*)d_in[22];
    const float* fc2w   = (const float*)d_in[23];
    const float* fc2b   = (const float*)d_in[24];
    float* out = (float*)d_out;

    int dev = 0;
    cudaGetDevice(&dev);
    int sms = 0;
    cudaDeviceGetAttribute(&sms, cudaDevAttrMultiProcessorCount, dev);
    if (sms <= 0) sms = 148;
    int occ = 0;
    cudaOccupancyMaxActiveBlocksPerMultiprocessor(&occ, mega_kernel, 256, 0);
    if (occ < 1) occ = 1;
    int grid = sms * occ;
    if (grid > 2048) grid = 2048;

    mega_kernel<<<grid, 256>>>(x, pseudo, L_idx, edge_w, edge_b,
                               mu0, sg0, mu1, sg1,
                               l1w0, l1b0, l2w0, l2b0,
                               l1w1, l1b1, l2w1, l2b1,
                               bn_g0, bn_b0);
    fc1_kernel<<<2048, 256>>>(fc1w, bn_g1, bn_b1);
    fc2_kernel<<<1, 448>>>(fc1b, fc2w, fc2b, out);
}

// round 14
// speedup vs baseline: 1.7878x; 1.7878x over previous
#include <cuda_runtime.h>
#include <cstdint>
#include <cstddef>

// ---------------------------------------------------------------------------
// Model_80985903333896: MoNet-style graph CNN.  B=8, M=4096, W=128, C=32.
// SINGLE persistent mega-kernel (R6 config + reduced-LDS ygemm tile):
//   P1: ygemm0 (1024 x 32-row tiles) + attn (256 units)
//   P2: gather0+BN0 | P3: ygemm1 | P4: gather1+BN1 | P5: fc1 | P6: fc2
// ygemm thread tile 2 rows x 4 outs: 6 LDS.128 per 16 FFMA2 (was 9/16) —
// P1-P4 measured L1-crossbar-bound (70.4% L1, 2.8% DRAM) in R13 split.
// fc1: R6 exact (plain loads — .cg regressed fc1 ~3x in R13).
// ---------------------------------------------------------------------------

#define EPSBN 1e-5f
typedef unsigned long long ull;

// ------------------------- scratch (__device__ globals) --------------------
__device__ float g_w0e[65536];
__device__ float g_w1e[65536];
__device__ int   g_nbr[65536];
__device__ float g_y1[1048576];   // (B*M, 32)
__device__ float g_y2[1048576];
__device__ float g_h1[1048576];
__device__ float g_h2[1048576];
__device__ float g_sum0[32], g_sq0[32], g_sum1[32], g_sq1[32];
__device__ float g_fc1acc[2048];  // (8, 256)
__device__ unsigned g_bar_count = 0;
__device__ unsigned g_bar_gen   = 0;

// ------------------------- packed f32x2 FMA helpers ------------------------
__device__ __forceinline__ ull pk2(float x, float y) {
    ull r; asm("mov.b64 %0, {%1, %2};" : "=l"(r) : "f"(x), "f"(y)); return r;
}
__device__ __forceinline__ void ffma2(ull& d, ull a, ull b) {
    asm("fma.rn.f32x2 %0, %1, %2, %0;" : "+l"(d) : "l"(a), "l"(b));
}
__device__ __forceinline__ float2 unpk(ull v) {
    float2 r; asm("mov.b64 {%0, %1}, %2;" : "=f"(r.x), "=f"(r.y) : "l"(v)); return r;
}

// ------------------------- software grid barrier ---------------------------
__device__ __forceinline__ void grid_barrier() {
    __syncthreads();
    if (threadIdx.x == 0) {
        __threadfence();
        unsigned gen = *((volatile unsigned*)&g_bar_gen);
        if (atomicAdd(&g_bar_count, 1u) == gridDim.x - 1u) {
            *((volatile unsigned*)&g_bar_count) = 0u;
            __threadfence();
            atomicExch(&g_bar_gen, gen + 1u);
        } else {
            while (*((volatile unsigned*)&g_bar_gen) == gen) __nanosleep(64);
            __threadfence();
        }
    }
    __syncthreads();
}

// ===========================================================================
// attn unit (256 edges): gaussian mixture -> 16-lane softmax -> dedup.
// Unit 0 also zero-inits the global accumulators (consumed after barrier 1).
// ===========================================================================
__device__ __forceinline__ void attn_unit(int bx,
    const float* __restrict__ pseudo, const int* __restrict__ L_idx,
    const float* __restrict__ edge_w, const float* __restrict__ edge_b,
    const float* __restrict__ mu0, const float* __restrict__ sg0,
    const float* __restrict__ mu1, const float* __restrict__ sg1)
{
    int tid = threadIdx.x;
    if (bx == 0) {
        if (tid < 32) {
            g_sum0[tid] = 0.f; g_sq0[tid] = 0.f;
            g_sum1[tid] = 0.f; g_sq1[tid] = 0.f;
        }
        for (int i = tid; i < 2048; i += 256) g_fc1acc[i] = 0.f;
    }
    int e = bx * 256 + tid;
    int i = e & 15;

    float p0 = pseudo[2 * e], p1 = pseudo[2 * e + 1];
    float emb[5];
#pragma unroll
    for (int d = 0; d < 5; d++)
        emb[d] = edge_w[2 * d] * p0 + edge_w[2 * d + 1] * p1 + edge_b[d];

    float w0 = 0.f, w1 = 0.f;
#pragma unroll
    for (int j = 0; j < 4; j++) {
        float q0 = 0.f, q1 = 0.f;
#pragma unroll
        for (int d = 0; d < 5; d++) {
            float u0 = emb[d] - mu0[j * 5 + d]; q0 += u0 * u0 * sg0[j * 5 + d];
            float u1 = emb[d] - mu1[j * 5 + d]; q1 += u1 * u1 * sg1[j * 5 + d];
        }
        w0 += expf(-0.5f * q0);
        w1 += expf(-0.5f * q1);
    }

    float m0 = w0, m1 = w1;
#pragma unroll
    for (int s = 8; s; s >>= 1) {
        m0 = fmaxf(m0, __shfl_xor_sync(0xffffffffu, m0, s, 16));
        m1 = fmaxf(m1, __shfl_xor_sync(0xffffffffu, m1, s, 16));
    }
    float e0 = expf(w0 - m0), e1 = expf(w1 - m1);
    float s0 = e0, s1 = e1;
#pragma unroll
    for (int s = 8; s; s >>= 1) {
        s0 += __shfl_xor_sync(0xffffffffu, s0, s, 16);
        s1 += __shfl_xor_sync(0xffffffffu, s1, s, 16);
    }
    float a0 = e0 / s0, a1 = e1 / s1;

    int nb = L_idx[e] & 4095;
    bool dup = false;
#pragma unroll
    for (int j = 0; j < 16; j++) {
        int nj = __shfl_sync(0xffffffffu, nb, j, 16);
        dup |= (j > i) && (nj == nb);
    }
    g_w0e[e] = dup ? 0.f : a0;
    g_w1e[e] = dup ? 0.f : a1;
    g_nbr[e] = nb;
}

// ===========================================================================
// ygemm unit: 32 rows x 64 outs, K chunked by 32 through smem.
// Thread tile 2 rows x 4 outs: per kk -> 2 x-LDS + 4 w-LDS per 16 FFMA2
// (0.375 LDS/FMA2, was 0.5625). Warp w: row-group w&3 (8 rows), out-group
// w>>2 (32 outs). Lane (r4 = lane>>3, o8 = lane&7): rows rg*8+r4*2+{0,1},
// outs og*32+o8+{0,8,16,24}. x-LDS: 4 distinct 16B (8-way bcast);
// w-LDS: 8 distinct 16B — single-phase each. Epilogue staged for
// coalesced stores. aux[0..31]=BN scale, aux[32..63]=BN shift.
// ===========================================================================
template<int KDIM, bool DO_BN>
__device__ __forceinline__ void ygemm_unit(int u,
    const float* __restrict__ src,
    const float* __restrict__ w1, const float* __restrict__ w2,
    const float* __restrict__ b1, const float* __restrict__ b2,
    float* s, const float* aux)
{
    constexpr int PADC = 36;
    float* sx = s;                 // 32*36
    float* sw = s + 32 * PADC;     // 64*36
    int tid = threadIdx.x;
    int warp = tid >> 5, lane = tid & 31;
    int r4 = lane >> 3, o8 = lane & 7;
    int rg = warp & 3, og = warp >> 2;
    int rowbase = u * 32;
    int lrow  = rg * 8 + r4 * 2;     // first of the row pair
    int obase = og * 32 + o8;        // outs obase + 8*j

    ull acc[2][4];
#pragma unroll
    for (int r = 0; r < 2; r++)
#pragma unroll
        for (int j = 0; j < 4; j++) acc[r][j] = 0ull;

#pragma unroll
    for (int c = 0; c < KDIM / 32; c++) {
        __syncthreads();   // also protects prev unit's epilogue reads
        {
            int r = tid >> 3, kq = tid & 7;
            float4 v = *(const float4*)(src + (size_t)(rowbase + r) * KDIM + c * 32 + kq * 4);
            if (DO_BN) {
                int k0 = kq * 4;   // KDIM==32 here
                v.x = fmaxf(0.f, fmaf(v.x, aux[k0],     aux[32 + k0]));
                v.y = fmaxf(0.f, fmaf(v.y, aux[k0 + 1], aux[32 + k0 + 1]));
                v.z = fmaxf(0.f, fmaf(v.z, aux[k0 + 2], aux[32 + k0 + 2]));
                v.w = fmaxf(0.f, fmaf(v.w, aux[k0 + 3], aux[32 + k0 + 3]));
            }
            *(float4*)&sx[r * PADC + kq * 4] = v;
        }
#pragma unroll
        for (int i = 0; i < 2; i++) {
            int idx = tid + i * 256;
            int oo = idx >> 3, kq = idx & 7;
            const float* wsrc = (oo < 32) ? (w1 + oo * KDIM) : (w2 + (oo - 32) * KDIM);
            *(float4*)&sw[oo * PADC + kq * 4] = *(const float4*)(wsrc + c * 32 + kq * 4);
        }
        __syncthreads();

#pragma unroll
        for (int kk = 0; kk < 8; kk++) {
            float4 xv0 = *(const float4*)&sx[lrow * PADC + kk * 4];
            float4 xv1 = *(const float4*)&sx[(lrow + 1) * PADC + kk * 4];
            ull x0a = pk2(xv0.x, xv0.y), x0b = pk2(xv0.z, xv0.w);
            ull x1a = pk2(xv1.x, xv1.y), x1b = pk2(xv1.z, xv1.w);
#pragma unroll
            for (int j = 0; j < 4; j++) {
                float4 wv = *(const float4*)&sw[(obase + 8 * j) * PADC + kk * 4];
                ull wa = pk2(wv.x, wv.y), wb = pk2(wv.z, wv.w);
                ffma2(acc[0][j], x0a, wa);
                ffma2(acc[0][j], x0b, wb);
                ffma2(acc[1][j], x1a, wa);
                ffma2(acc[1][j], x1b, wb);
            }
        }
    }
    __syncthreads();
#pragma unroll
    for (int r = 0; r < 2; r++)
#pragma unroll
        for (int j = 0; j < 4; j++) {
            float2 v = unpk(acc[r][j]);
            s[(lrow + r) * 65 + obase + 8 * j] = v.x + v.y;
        }
    __syncthreads();
#pragma unroll
    for (int i = 0; i < 2; i++) {
        int idx = tid + i * 256;     // 512 float4 = 32 rows x 16
        int r = idx >> 4, q = idx & 15;
        int c0 = q * 4;
        float4 v;
        v.x = s[r * 65 + c0];
        v.y = s[r * 65 + c0 + 1];
        v.z = s[r * 65 + c0 + 2];
        v.w = s[r * 65 + c0 + 3];
        int grow = rowbase + r;
        if (c0 < 32) {
            *(float4*)&g_y1[grow * 32 + c0] = v;
        } else {
            int oc = c0 - 32;
            v.x += b1[oc]     + b2[oc];
            v.y += b1[oc + 1] + b2[oc + 1];
            v.z += b1[oc + 2] + b2[oc + 2];
            v.w += b1[oc + 3] + b2[oc + 3];
            *(float4*)&g_y2[grow * 32 + oc] = v;
        }
    }
}

// ===========================================================================
// gather phase: warp-unit = (node m, batch pair). 16384 units grid-strided
// over all warps. lane = channel. + BN stats (block-reduced, 1 atomic set).
// ===========================================================================
template<int LAYER>
__device__ __forceinline__ void gather_phase(float* red)
{
    const float* __restrict__ weff = (LAYER == 0) ? g_w0e : g_w1e;
    float* __restrict__ h   = (LAYER == 0) ? g_h1 : g_h2;
    float* gsum = (LAYER == 0) ? g_sum0 : g_sum1;
    float* gsq  = (LAYER == 0) ? g_sq0  : g_sq1;

    int tid = threadIdx.x, lane = tid & 31, warp = tid >> 5;
    if (tid < 64) red[tid] = 0.f;
    __syncthreads();

    int nw = gridDim.x * 8;
    float lsum = 0.f, lsq = 0.f;
    for (int u = blockIdx.x * 8 + warp; u < 16384; u += nw) {
        int m = u >> 2;
        int b0 = (u & 3) << 1;
        float wv = 0.f; int nv = 0;
        if (lane < 16) {
            wv = weff[m * 16 + lane];
            nv = g_nbr[m * 16 + lane];
        }
        int row0 = (b0 << 12) + m;
        float a0 = g_y2[(size_t)row0 * 32 + lane];
        float a1 = g_y2[(size_t)(row0 + 4096) * 32 + lane];
#pragma unroll
        for (int i = 0; i < 16; i++) {
            float wi = __shfl_sync(0xffffffffu, wv, i);
            int   ni = __shfl_sync(0xffffffffu, nv, i);
            int rn = (b0 << 12) + ni;
            a0 = fmaf(wi, g_y1[(size_t)rn * 32 + lane], a0);
            a1 = fmaf(wi, g_y1[(size_t)(rn + 4096) * 32 + lane], a1);
        }
        h[(size_t)row0 * 32 + lane] = a0;
        h[(size_t)(row0 + 4096) * 32 + lane] = a1;
        lsum += a0 + a1;
        lsq  += a0 * a0 + a1 * a1;
    }
    atomicAdd(&red[lane], lsum);
    atomicAdd(&red[32 + lane], lsq);
    __syncthreads();
    if (tid < 32) {
        atomicAdd(&gsum[tid], red[tid]);
        atomicAdd(&gsq[tid],  red[32 + tid]);
    }
}

// ===========================================================================
// fc1 phase (R6 exact): unit = (out-group og of 32, k-chunk kc of 512).
// 2048 units grid-strided. Acts (BN1+relu) staged to smem (pad 520).
// Warp = 4 outs; lane-halves split batches; acc 4 outs x 4 b f32x2.
// Butterfly distribute-reduce over 16 lanes; 32 atomics/warp/unit.
// ===========================================================================
__device__ __forceinline__ void fc1_phase(
    const float* __restrict__ fc1w, float* s, const float* aux)
{
    int tid = threadIdx.x, lane = tid & 31, warp = tid >> 5;
    int l16 = lane & 15;
    int bbase = (lane >> 4) * 4;

    for (int u = blockIdx.x; u < 2048; u += gridDim.x) {
        __syncthreads();
        int og = u >> 8, kc = u & 255;
        int kbase = kc * 512;
        // stage acts: 8 batches x 512 k, BN+relu, rows padded to 520
#pragma unroll
        for (int i = 0; i < 4; i++) {
            int idx = tid + i * 256;
            int b = idx >> 7, kq = idx & 127;
            float4 v = *(const float4*)(&g_h2[(size_t)b * 131072 + kbase + kq * 4]);
            int c0 = (kq * 4) & 31;
            v.x = fmaxf(0.f, fmaf(v.x, aux[c0],     aux[32 + c0]));
            v.y = fmaxf(0.f, fmaf(v.y, aux[c0 + 1], aux[32 + c0 + 1]));
            v.z = fmaxf(0.f, fmaf(v.z, aux[c0 + 2], aux[32 + c0 + 2]));
            v.w = fmaxf(0.f, fmaf(v.w, aux[c0 + 3], aux[32 + c0 + 3]));
            *(float4*)&s[b * 520 + kq * 4] = v;
        }
        __syncthreads();

        const float* wp = fc1w + (size_t)(og * 32 + warp * 4) * 131072 + kbase;
        ull acc[4][4];
#pragma unroll
        for (int o4 = 0; o4 < 4; o4++)
#pragma unroll
            for (int bb = 0; bb < 4; bb++) acc[o4][bb] = 0ull;

#pragma unroll
        for (int t = 0; t < 8; t++) {
            int k0 = t * 64 + l16 * 4;
            float4 w[4], a[4];
#pragma unroll
            for (int o4 = 0; o4 < 4; o4++)
                w[o4] = *(const float4*)(wp + (size_t)o4 * 131072 + k0);
#pragma unroll
            for (int bb = 0; bb < 4; bb++)
                a[bb] = *(const float4*)&s[(bbase + bb) * 520 + k0];
#pragma unroll
            for (int o4 = 0; o4 < 4; o4++) {
                ull w01 = pk2(w[o4].x, w[o4].y), w23 = pk2(w[o4].z, w[o4].w);
#pragma unroll
                for (int bb = 0; bb < 4; bb++) {
                    ffma2(acc[o4][bb], w01, pk2(a[bb].x, a[bb].y));
                    ffma2(acc[o4][bb], w23, pk2(a[bb].z, a[bb].w));
                }
            }
        }

        // butterfly distribute-reduce within each 16-lane half
        float v[16];
#pragma unroll
        for (int o4 = 0; o4 < 4; o4++)
#pragma unroll
            for (int bb = 0; bb < 4; bb++) {
                float2 t2 = unpk(acc[o4][bb]);
                v[o4 * 4 + bb] = t2.x + t2.y;
            }
#pragma unroll
        for (int sr = 8; sr >= 1; sr >>= 1) {
            bool up = (l16 & sr) != 0;
#pragma unroll
            for (int i = 0; i < sr; i++) {
                float send = up ? v[i] : v[i + sr];
                float got  = __shfl_xor_sync(0xffffffffu, send, sr);
                v[i] = (up ? v[i + sr] : v[i]) + got;
            }
        }
        int o4 = l16 >> 2, bb = l16 & 3;
        atomicAdd(&g_fc1acc[(bbase + bb) * 256 + og * 32 + warp * 4 + o4], v[0]);
    }
}

// ===========================================================================
// mega-kernel
// ===========================================================================
__global__ void __launch_bounds__(256, 3) mega_kernel(
    const float* __restrict__ x,
    const float* __restrict__ pseudo, const int* __restrict__ L_idx,
    const float* __restrict__ edge_w, const float* __restrict__ edge_b,
    const float* __restrict__ mu0, const float* __restrict__ sg0,
    const float* __restrict__ mu1, const float* __restrict__ sg1,
    const float* __restrict__ l1w0, const float* __restrict__ l1b0,
    const float* __restrict__ l2w0, const float* __restrict__ l2b0,
    const float* __restrict__ l1w1, const float* __restrict__ l1b1,
    const float* __restrict__ l2w1, const float* __restrict__ l2b1,
    const float* __restrict__ bn_g0, const float* __restrict__ bn_b0,
    const float* __restrict__ bn_g1, const float* __restrict__ bn_b1,
    const float* __restrict__ fc1w, const float* __restrict__ fc1b,
    const float* __restrict__ fc2w, const float* __restrict__ fc2b,
    float* __restrict__ out)
{
    __shared__ __align__(16) float s[4608];
    __shared__ float aux[64];
    __shared__ float red[64];
    int tid = threadIdx.x;

    // ---- P1: ygemm0 (units 0..1023) + attn (1024..1279) ----
    for (int u = blockIdx.x; u < 1280; u += gridDim.x) {
        if (u < 1024)
            ygemm_unit<128, false>(u, x, l1w0, l2w0, l1b0, l2b0, s, aux);
        else
            attn_unit(u - 1024, pseudo, L_idx, edge_w, edge_b, mu0, sg0, mu1, sg1);
    }
    grid_barrier();

    // ---- P2: gather0 + BN0 stats ----
    gather_phase<0>(red);
    grid_barrier();

    // ---- P3: ygemm1 (BN0 applied on load) ----
    if (tid < 32) {
        const float inv_n = 1.0f / 32768.0f;
        float mean = g_sum0[tid] * inv_n;
        float var  = g_sq0[tid] * inv_n - mean * mean;
        float sc   = bn_g0[tid] * rsqrtf(var + EPSBN);
        aux[tid] = sc;
        aux[32 + tid] = bn_b0[tid] - mean * sc;
    }
    __syncthreads();
    for (int u = blockIdx.x; u < 1024; u += gridDim.x)
        ygemm_unit<32, true>(u, g_h1, l1w1, l2w1, l1b1, l2b1, s, aux);
    grid_barrier();

    // ---- P4: gather1 + BN1 stats ----
    gather_phase<1>(red);
    grid_barrier();

    // ---- P5: fc1 (BN1 applied on load) ----
    if (tid < 32) {
        const float inv_n = 1.0f / 32768.0f;
        float mean = g_sum1[tid] * inv_n;
        float var  = g_sq1[tid] * inv_n - mean * mean;
        float sc   = bn_g1[tid] * rsqrtf(var + EPSBN);
        aux[tid] = sc;
        aux[32 + tid] = bn_b1[tid] - mean * sc;
    }
    __syncthreads();
    fc1_phase(fc1w, s, aux);
    grid_barrier();

    // ---- P6: fc2 -> out. warp per (b, o). ----
    {
        int warp = tid >> 5, lane = tid & 31;
        int gw = blockIdx.x * 8 + warp;
        if (gw < 424) {
            int b = gw / 53, o = gw - b * 53;
            float acc = 0.f;
#pragma unroll
            for (int j = 0; j < 8; j++) {
                int k = lane * 8 + j;
                float f = fmaxf(0.f, g_fc1acc[b * 256 + k] + fc1b[k]);
                acc = fmaf(f, fc2w[o * 256 + k], acc);
            }
#pragma unroll
            for (int sft = 16; sft; sft >>= 1)
                acc += __shfl_xor_sync(0xffffffffu, acc, sft);
            if (lane == 0) out[b * 53 + o] = acc + fc2b[o];
        }
    }
}

// ===========================================================================
extern "C" void kernel_launch(void* const* d_in, const int* in_sizes, int n_in,
                              void* d_out, int out_size)
{
    const float* x      = (const float*)d_in[0];
    const float* pseudo = (const float*)d_in[1];
    const int*   L_idx  = (const int*)  d_in[2];
    const float* edge_w = (const float*)d_in[3];
    const float* edge_b = (const float*)d_in[4];
    const float* mu0    = (const float*)d_in[5];
    const float* sg0    = (const float*)d_in[6];
    const float* mu1    = (const float*)d_in[7];
    const float* sg1    = (const float*)d_in[8];
    const float* l1w0   = (const float*)d_in[9];
    const float* l1b0   = (const float*)d_in[10];
    const float* l2w0   = (const float*)d_in[11];
    const float* l2b0   = (const float*)d_in[12];
    const float* l1w1   = (const float*)d_in[13];
    const float* l1b1   = (const float*)d_in[14];
    const float* l2w1   = (const float*)d_in[15];
    const float* l2b1   = (const float*)d_in[16];
    const float* bn_g0  = (const float*)d_in[17];
    const float* bn_b0  = (const float*)d_in[18];
    const float* bn_g1  = (const float*)d_in[19];
    const float* bn_b1  = (const float*)d_in[20];
    const float* fc1w   = (const float*)d_in[21];
    const float* fc1b   = (const float*)d_in[22];
    const float* fc2w   = (const float*)d_in[23];
    const float* fc2b   = (const float*)d_in[24];
    float* out = (float*)d_out;

    int dev = 0;
    cudaGetDevice(&dev);
    int sms = 0;
    cudaDeviceGetAttribute(&sms, cudaDevAttrMultiProcessorCount, dev);
    if (sms <= 0) sms = 148;
    int occ = 0;
    cudaOccupancyMaxActiveBlocksPerMultiprocessor(&occ, mega_kernel, 256, 0);
    if (occ < 1) occ = 1;
    int grid = sms * occ;
    if (grid > 2048) grid = 2048;

    mega_kernel<<<grid, 256>>>(x, pseudo, L_idx, edge_w, edge_b,
                               mu0, sg0, mu1, sg1,
                               l1w0, l1b0, l2w0, l2b0,
                               l1w1, l1b1, l2w1, l2b1,
                               bn_g0, bn_b0, bn_g1, bn_b1,
                               fc1w, fc1b, fc2w, fc2b, out);
}